// round 1
// baseline (speedup 1.0000x reference)
#include <cuda_runtime.h>
#include <math.h>

#define BB 4
#define NN 256
#define TT 128
#define FIN 64
#define KK 8
#define HH 256
#define EE 8

// Scratch (static device globals — no allocation allowed)
__device__ float g_ht[(size_t)BB * TT * NN * HH];     // 128 MB: h transposed (B,T,N,H)
__device__ float g_As[(size_t)BB * KK * NN * NN];     // 8 MB: alpha[b,k] * A_norm[k]
__device__ float g_ctx_part[BB * 16 * FIN];
__device__ float g_alpha[BB * KK];

__device__ __forceinline__ float gelu_exact(float v) {
    return 0.5f * v * (1.0f + erff(v * 0.70710678118654752440f));
}

// ---------------------------------------------------------------------------
// K1: partial sums for ctx = x.mean(axis=(1,2)); deterministic (no atomics)
// grid 64 = B*16 chunks, 256 threads
// ---------------------------------------------------------------------------
__global__ void k1_ctx(const float* __restrict__ x) {
    int b = blockIdx.x >> 4;
    int ch = blockIdx.x & 15;
    int f = threadIdx.x & 63;
    int part = threadIdx.x >> 6;
    const float* xb = x + (size_t)b * NN * TT * FIN;
    float s = 0.f;
    int nt0 = ch * 2048;
    for (int nt = nt0 + part; nt < nt0 + 2048; nt += 4)
        s += xb[(size_t)nt * FIN + f];
    __shared__ float sred[256];
    sred[threadIdx.x] = s;
    __syncthreads();
    if (part == 0) {
        float tot = sred[f] + sred[64 + f] + sred[128 + f] + sred[192 + f];
        g_ctx_part[(b * 16 + ch) * FIN + f] = tot;
    }
}

// ---------------------------------------------------------------------------
// K2: ctx MLP + gate MLP -> alpha[b,k]. 1 block, 32 threads (one per (b,k)).
// ---------------------------------------------------------------------------
__global__ void k2_gate(const float* __restrict__ lag_embed,
                        const float* __restrict__ ctx_w1, const float* __restrict__ ctx_b1,
                        const float* __restrict__ ctx_w2, const float* __restrict__ ctx_b2,
                        const float* __restrict__ gate_w1, const float* __restrict__ gate_b1,
                        const float* __restrict__ gate_w2, const float* __restrict__ gate_b2) {
    int tid = threadIdx.x;
    if (tid >= BB * KK) return;
    int b = tid >> 3, k = tid & 7;
    float ctx[FIN];
    for (int f = 0; f < FIN; f++) {
        float s = 0.f;
        for (int ch = 0; ch < 16; ch++) s += g_ctx_part[(b * 16 + ch) * FIN + f];
        ctx[f] = s * (1.0f / (NN * TT));
    }
    float t1[EE];
    for (int e = 0; e < EE; e++) {
        float s = ctx_b1[e];
        for (int f = 0; f < FIN; f++) s += ctx[f] * ctx_w1[f * EE + e];
        t1[e] = gelu_exact(s);
    }
    float cf[EE];
    for (int e2 = 0; e2 < EE; e2++) {
        float s = ctx_b2[e2];
        for (int e = 0; e < EE; e++) s += t1[e] * ctx_w2[e * EE + e2];
        cf[e2] = s;
    }
    float gi[2 * EE];
    for (int e = 0; e < EE; e++) { gi[e] = lag_embed[k * EE + e]; gi[EE + e] = cf[e]; }
    float hid[EE];
    for (int e = 0; e < EE; e++) {
        float s = gate_b1[e];
        for (int j = 0; j < 2 * EE; j++) s += gi[j] * gate_w1[j * EE + e];
        hid[e] = gelu_exact(s);
    }
    float val = gate_b2[0];
    for (int e = 0; e < EE; e++) val += hid[e] * gate_w2[e];
    g_alpha[tid] = 1.0f / (1.0f + expf(-val));
}

// ---------------------------------------------------------------------------
// K3: g_As[b,k,i,j] = alpha[b,k] * A[k,i,j] / max(rowsum, 1e-8)
// grid 2048 = K*N rows, 256 threads
// ---------------------------------------------------------------------------
__global__ void k3_scaleA(const float* __restrict__ A_list) {
    int k = blockIdx.x >> 8;
    int i = blockIdx.x & 255;
    int tid = threadIdx.x;
    float a = A_list[((size_t)k * NN + i) * NN + tid];
    __shared__ float sred[256];
    sred[tid] = a;
    __syncthreads();
    for (int s = 128; s > 0; s >>= 1) {
        if (tid < s) sred[tid] += sred[tid + s];
        __syncthreads();
    }
    float inv = 1.0f / fmaxf(sred[0], 1e-8f);
    float an = a * inv;
#pragma unroll
    for (int b = 0; b < BB; b++)
        g_As[(((size_t)b * KK + k) * NN + i) * NN + tid] = g_alpha[b * KK + k] * an;
}

// ---------------------------------------------------------------------------
// K4: g_ht[b,t,n,h] = sum_f x[b,n,t,f]*in_w[f,h] + in_b[h]
// grid 2048 = (b, t, nblk of 64), 256 threads (thread = output column h)
// ---------------------------------------------------------------------------
__global__ void __launch_bounds__(256) k4_h(const float* __restrict__ x,
                                            const float* __restrict__ in_w,
                                            const float* __restrict__ in_b) {
    int bid = blockIdx.x;
    int nblk = bid & 3;
    int t = (bid >> 2) & 127;
    int b = bid >> 9;
    int tid = threadIdx.x;
    __shared__ float xs[64 * 68];
    float w[FIN];
#pragma unroll
    for (int f = 0; f < FIN; f++) w[f] = in_w[f * HH + tid];
    float bias = in_b[tid];
    for (int idx = tid; idx < 64 * 64; idx += 256) {
        int n = idx >> 6, f = idx & 63;
        xs[n * 68 + f] = x[(((size_t)b * NN + nblk * 64 + n) * TT + t) * FIN + f];
    }
    __syncthreads();
    float* orow = g_ht + (((size_t)b * TT + t) * NN + nblk * 64) * HH;
    for (int n = 0; n < 64; n++) {
        float acc = bias;
        const float4* xr = (const float4*)&xs[n * 68];
#pragma unroll
        for (int f4 = 0; f4 < 16; f4++) {
            float4 xv = xr[f4];
            acc += xv.x * w[f4 * 4 + 0];
            acc += xv.y * w[f4 * 4 + 1];
            acc += xv.z * w[f4 * 4 + 2];
            acc += xv.w * w[f4 * 4 + 3];
        }
        orow[(size_t)n * HH + tid] = acc;
    }
}

// ---------------------------------------------------------------------------
// K5: fused  OUT = sum_k As[b,k] @ h_t[b,t-k]  ->  Z = OUT @ out_w + out_b
//     -> res = Z + h_t[b,t] -> LayerNorm -> GELU -> store transposed
// grid 2048 = (b, t, iblk of 64 rows). 256 threads, 8x8 microtile each.
// ---------------------------------------------------------------------------
#define SOUT_LD 260
#define SA_LD 33

__global__ void __launch_bounds__(256, 2) k5_main(const float* __restrict__ out_w,
                                                  const float* __restrict__ out_b,
                                                  const float* __restrict__ ln_g,
                                                  const float* __restrict__ ln_b,
                                                  float* __restrict__ out) {
    extern __shared__ float smem[];
    float* s_out = smem;                       // 64 x 260
    float* s_a = smem + 64 * SOUT_LD;          // 64 x 33
    float* s_h = s_a + 64 * SA_LD;             // 32 x 256

    int bid = blockIdx.x;
    int iblk = bid & 3;
    int t = (bid >> 2) & 127;
    int b = bid >> 9;
    int tid = threadIdx.x;
    int rg = tid >> 5, cg = tid & 31;
    int i0 = iblk * 64;

    float acc[8][8];
#pragma unroll
    for (int r = 0; r < 8; r++)
#pragma unroll
        for (int c = 0; c < 8; c++) acc[r][c] = 0.f;

    // GEMM1: accumulate over lags k and j-tiles
    for (int k = 0; k < KK; k++) {
        int ts = t - k;
        if (ts < 0) break;  // uniform across block; ts only decreases with k
        const float* Ab = g_As + (((size_t)b * KK + k) * NN + i0) * NN;
        const float4* Hb = (const float4*)(g_ht + ((size_t)(b * TT + ts) * NN) * HH);
        for (int jt = 0; jt < 8; jt++) {
            for (int idx = tid; idx < 64 * 32; idx += 256) {
                int i = idx >> 5, j = idx & 31;
                s_a[i * SA_LD + j] = Ab[(size_t)i * NN + jt * 32 + j];
            }
            {
                float4* dsth = (float4*)s_h;
                const float4* srch = Hb + jt * 32 * 64;
                for (int idx = tid; idx < 2048; idx += 256) dsth[idx] = srch[idx];
            }
            __syncthreads();
#pragma unroll 4
            for (int j = 0; j < 32; j++) {
                float4 b0 = *(const float4*)&s_h[j * 256 + cg * 8];
                float4 b1 = *(const float4*)&s_h[j * 256 + cg * 8 + 4];
#pragma unroll
                for (int r = 0; r < 8; r++) {
                    float a = s_a[(rg * 8 + r) * SA_LD + j];
                    acc[r][0] += a * b0.x; acc[r][1] += a * b0.y;
                    acc[r][2] += a * b0.z; acc[r][3] += a * b0.w;
                    acc[r][4] += a * b1.x; acc[r][5] += a * b1.y;
                    acc[r][6] += a * b1.z; acc[r][7] += a * b1.w;
                }
            }
            __syncthreads();
        }
    }

    // stage OUT to smem (row-major, warp writes one row -> conflict-free)
#pragma unroll
    for (int r = 0; r < 8; r++) {
        *(float4*)&s_out[(rg * 8 + r) * SOUT_LD + cg * 8] =
            make_float4(acc[r][0], acc[r][1], acc[r][2], acc[r][3]);
        *(float4*)&s_out[(rg * 8 + r) * SOUT_LD + cg * 8 + 4] =
            make_float4(acc[r][4], acc[r][5], acc[r][6], acc[r][7]);
    }
    __syncthreads();

    // GEMM2: Z = OUT @ out_w + out_b
    float acc2[8][8];
    {
        float4 ob0 = *(const float4*)&out_b[cg * 8];
        float4 ob1 = *(const float4*)&out_b[cg * 8 + 4];
#pragma unroll
        for (int r = 0; r < 8; r++) {
            acc2[r][0] = ob0.x; acc2[r][1] = ob0.y; acc2[r][2] = ob0.z; acc2[r][3] = ob0.w;
            acc2[r][4] = ob1.x; acc2[r][5] = ob1.y; acc2[r][6] = ob1.z; acc2[r][7] = ob1.w;
        }
    }
    for (int jt = 0; jt < 8; jt++) {
        {
            const float4* srcw = (const float4*)(out_w + (size_t)jt * 32 * HH);
            float4* dsth = (float4*)s_h;
            for (int idx = tid; idx < 2048; idx += 256) dsth[idx] = srcw[idx];
        }
        __syncthreads();
#pragma unroll 4
        for (int j = 0; j < 32; j++) {
            float4 b0 = *(const float4*)&s_h[j * 256 + cg * 8];
            float4 b1 = *(const float4*)&s_h[j * 256 + cg * 8 + 4];
#pragma unroll
            for (int r = 0; r < 8; r++) {
                float a = s_out[(rg * 8 + r) * SOUT_LD + jt * 32 + j];
                acc2[r][0] += a * b0.x; acc2[r][1] += a * b0.y;
                acc2[r][2] += a * b0.z; acc2[r][3] += a * b0.w;
                acc2[r][4] += a * b1.x; acc2[r][5] += a * b1.y;
                acc2[r][6] += a * b1.z; acc2[r][7] += a * b1.w;
            }
        }
        __syncthreads();
    }

    // Epilogue: residual + LayerNorm(H) + GELU + transposed store
    const float* htrow = g_ht + (((size_t)b * TT + t) * NN + i0) * HH;
    float lg[8], lb[8];
    {
        float4 g0 = *(const float4*)&ln_g[cg * 8];
        float4 g1 = *(const float4*)&ln_g[cg * 8 + 4];
        float4 bb0 = *(const float4*)&ln_b[cg * 8];
        float4 bb1 = *(const float4*)&ln_b[cg * 8 + 4];
        lg[0] = g0.x; lg[1] = g0.y; lg[2] = g0.z; lg[3] = g0.w;
        lg[4] = g1.x; lg[5] = g1.y; lg[6] = g1.z; lg[7] = g1.w;
        lb[0] = bb0.x; lb[1] = bb0.y; lb[2] = bb0.z; lb[3] = bb0.w;
        lb[4] = bb1.x; lb[5] = bb1.y; lb[6] = bb1.z; lb[7] = bb1.w;
    }
#pragma unroll
    for (int r = 0; r < 8; r++) {
        int i = rg * 8 + r;
        float4 h0 = *(const float4*)&htrow[(size_t)i * HH + cg * 8];
        float4 h1 = *(const float4*)&htrow[(size_t)i * HH + cg * 8 + 4];
        float res[8];
        res[0] = acc2[r][0] + h0.x; res[1] = acc2[r][1] + h0.y;
        res[2] = acc2[r][2] + h0.z; res[3] = acc2[r][3] + h0.w;
        res[4] = acc2[r][4] + h1.x; res[5] = acc2[r][5] + h1.y;
        res[6] = acc2[r][6] + h1.z; res[7] = acc2[r][7] + h1.w;
        float s1 = 0.f, s2 = 0.f;
#pragma unroll
        for (int c = 0; c < 8; c++) { s1 += res[c]; s2 += res[c] * res[c]; }
#pragma unroll
        for (int off = 16; off > 0; off >>= 1) {
            s1 += __shfl_xor_sync(0xffffffffu, s1, off);
            s2 += __shfl_xor_sync(0xffffffffu, s2, off);
        }
        float mu = s1 * (1.0f / HH);
        float var = s2 * (1.0f / HH) - mu * mu;
        float rstd = rsqrtf(var + 1e-5f);
        float o[8];
#pragma unroll
        for (int c = 0; c < 8; c++) {
            float y = (res[c] - mu) * rstd * lg[c] + lb[c];
            o[c] = gelu_exact(y);
        }
        float* op = out + (((size_t)b * NN + i0 + i) * TT + t) * HH + cg * 8;
        *(float4*)&op[0] = make_float4(o[0], o[1], o[2], o[3]);
        *(float4*)&op[4] = make_float4(o[4], o[5], o[6], o[7]);
    }
}

// ---------------------------------------------------------------------------
extern "C" void kernel_launch(void* const* d_in, const int* in_sizes, int n_in,
                              void* d_out, int out_size) {
    const float* x = (const float*)d_in[0];
    const float* A_list = (const float*)d_in[1];
    const float* in_w = (const float*)d_in[2];
    const float* in_b = (const float*)d_in[3];
    const float* out_w = (const float*)d_in[4];
    const float* out_b = (const float*)d_in[5];
    const float* lag_embed = (const float*)d_in[6];
    const float* ctx_w1 = (const float*)d_in[7];
    const float* ctx_b1 = (const float*)d_in[8];
    const float* ctx_w2 = (const float*)d_in[9];
    const float* ctx_b2 = (const float*)d_in[10];
    const float* gate_w1 = (const float*)d_in[11];
    const float* gate_b1 = (const float*)d_in[12];
    const float* gate_w2 = (const float*)d_in[13];
    const float* gate_b2 = (const float*)d_in[14];
    const float* ln_g = (const float*)d_in[15];
    const float* ln_b = (const float*)d_in[16];
    float* out = (float*)d_out;

    size_t smem5 = (size_t)(64 * SOUT_LD + 64 * SA_LD + 32 * 256) * sizeof(float);
    cudaFuncSetAttribute(k5_main, cudaFuncAttributeMaxDynamicSharedMemorySize, (int)smem5);

    k1_ctx<<<64, 256>>>(x);
    k2_gate<<<1, 32>>>(lag_embed, ctx_w1, ctx_b1, ctx_w2, ctx_b2,
                       gate_w1, gate_b1, gate_w2, gate_b2);
    k3_scaleA<<<2048, 256>>>(A_list);
    k4_h<<<2048, 256>>>(x, in_w, in_b);
    k5_main<<<2048, 256, smem5>>>(out_w, out_b, ln_g, ln_b, out);
}

// round 6
// speedup vs baseline: 2.6158x; 2.6158x over previous
#include <cuda_runtime.h>
#include <math.h>
#include <stdint.h>

#define BB 4
#define NN 256
#define TT 128
#define FIN 64
#define KK 8
#define HH 256
#define EE 8

// ---------------- scratch (static device globals; no allocation) ----------------
__device__ float g_h[(size_t)BB * TT * NN * HH];    // 128 MB: h (residual), h contig
__device__ float g_hw[(size_t)BB * TT * NN * HH];   // 128 MB: hw = h@out_w, h2 contig
__device__ float g_As[(size_t)BB * KK * NN * NN];   // 8 MB: alpha*A_norm (tf32-rounded)
__device__ float g_W2[FIN * HH];                    // in_w @ out_w
__device__ float g_b2[HH];                          // in_b @ out_w
__device__ float g_ctx_part[BB * 16 * FIN];
__device__ float g_alpha[BB * KK];

__device__ __forceinline__ float gelu_exact(float v) {
    return 0.5f * v * (1.0f + erff(v * 0.70710678118654752440f));
}
// tf32 round-to-nearest: cvt.rna.tf32.f32 requires .b32 destination
__device__ __forceinline__ float to_tf32(float x) {
    uint32_t r;
    asm("cvt.rna.tf32.f32 %0, %1;" : "=r"(r) : "f"(x));
    return __uint_as_float(r);
}
__device__ __forceinline__ uint32_t smem_u32(const void* p) {
    uint32_t a;
    asm("{ .reg .u64 t; cvta.to.shared.u64 t, %1; cvt.u32.u64 %0, t; }" : "=r"(a) : "l"(p));
    return a;
}
__device__ __forceinline__ void cp16(uint32_t dst, const void* src) {
    asm volatile("cp.async.cg.shared.global [%0], [%1], 16;" :: "r"(dst), "l"(src));
}
#define CP_COMMIT() asm volatile("cp.async.commit_group;" ::: "memory")
#define CP_WAIT0() asm volatile("cp.async.wait_group 0;" ::: "memory")
#define CP_WAIT1() asm volatile("cp.async.wait_group 1;" ::: "memory")

#define MMA_TF32(d, a, b) \
    asm volatile("mma.sync.aligned.m16n8k8.row.col.f32.tf32.tf32.f32 " \
        "{%0,%1,%2,%3}, {%4,%5,%6,%7}, {%8,%9}, {%0,%1,%2,%3};" \
        : "+f"((d)[0]), "+f"((d)[1]), "+f"((d)[2]), "+f"((d)[3]) \
        : "r"((a)[0]), "r"((a)[1]), "r"((a)[2]), "r"((a)[3]), "r"((b)[0]), "r"((b)[1]))

// ---------------------------------------------------------------------------
// K1: partial sums for ctx = x.mean(axis=(1,2))
// ---------------------------------------------------------------------------
__global__ void k1_ctx(const float* __restrict__ x) {
    int b = blockIdx.x >> 4;
    int ch = blockIdx.x & 15;
    int f = threadIdx.x & 63;
    int part = threadIdx.x >> 6;
    const float* xb = x + (size_t)b * NN * TT * FIN;
    float s = 0.f;
    int nt0 = ch * 2048;
    for (int nt = nt0 + part; nt < nt0 + 2048; nt += 4)
        s += xb[(size_t)nt * FIN + f];
    __shared__ float sred[256];
    sred[threadIdx.x] = s;
    __syncthreads();
    if (part == 0) {
        float tot = sred[f] + sred[64 + f] + sred[128 + f] + sred[192 + f];
        g_ctx_part[(b * 16 + ch) * FIN + f] = tot;
    }
}

// ---------------------------------------------------------------------------
// K2: ctx MLP + gate MLP -> alpha[b,k]
// ---------------------------------------------------------------------------
__global__ void k2_gate(const float* __restrict__ lag_embed,
                        const float* __restrict__ ctx_w1, const float* __restrict__ ctx_b1,
                        const float* __restrict__ ctx_w2, const float* __restrict__ ctx_b2,
                        const float* __restrict__ gate_w1, const float* __restrict__ gate_b1,
                        const float* __restrict__ gate_w2, const float* __restrict__ gate_b2) {
    int tid = threadIdx.x;
    if (tid >= BB * KK) return;
    int b = tid >> 3, k = tid & 7;
    float ctx[FIN];
    for (int f = 0; f < FIN; f++) {
        float s = 0.f;
        for (int ch = 0; ch < 16; ch++) s += g_ctx_part[(b * 16 + ch) * FIN + f];
        ctx[f] = s * (1.0f / (NN * TT));
    }
    float t1[EE];
    for (int e = 0; e < EE; e++) {
        float s = ctx_b1[e];
        for (int f = 0; f < FIN; f++) s += ctx[f] * ctx_w1[f * EE + e];
        t1[e] = gelu_exact(s);
    }
    float cf[EE];
    for (int e2 = 0; e2 < EE; e2++) {
        float s = ctx_b2[e2];
        for (int e = 0; e < EE; e++) s += t1[e] * ctx_w2[e * EE + e2];
        cf[e2] = s;
    }
    float gi[2 * EE];
    for (int e = 0; e < EE; e++) { gi[e] = lag_embed[k * EE + e]; gi[EE + e] = cf[e]; }
    float hid[EE];
    for (int e = 0; e < EE; e++) {
        float s = gate_b1[e];
        for (int j = 0; j < 2 * EE; j++) s += gi[j] * gate_w1[j * EE + e];
        hid[e] = gelu_exact(s);
    }
    float val = gate_b2[0];
    for (int e = 0; e < EE; e++) val += hid[e] * gate_w2[e];
    g_alpha[tid] = 1.0f / (1.0f + expf(-val));
}

// ---------------------------------------------------------------------------
// K3: g_As[b,k,i,j] = tf32( alpha[b,k] * A[k,i,j] / max(rowsum, 1e-8) )
// ---------------------------------------------------------------------------
__global__ void k3_scaleA(const float* __restrict__ A_list) {
    int k = blockIdx.x >> 8;
    int i = blockIdx.x & 255;
    int tid = threadIdx.x;
    float a = A_list[((size_t)k * NN + i) * NN + tid];
    __shared__ float sred[256];
    sred[tid] = a;
    __syncthreads();
    for (int s = 128; s > 0; s >>= 1) {
        if (tid < s) sred[tid] += sred[tid + s];
        __syncthreads();
    }
    float inv = 1.0f / fmaxf(sred[0], 1e-8f);
    float an = a * inv;
#pragma unroll
    for (int b = 0; b < BB; b++)
        g_As[(((size_t)b * KK + k) * NN + i) * NN + tid] = to_tf32(g_alpha[b * KK + k] * an);
}

// ---------------------------------------------------------------------------
// K3c: g_W2 = in_w @ out_w  (f,h2), g_b2 = in_b @ out_w. grid 65 x 256
// ---------------------------------------------------------------------------
__global__ void k3c_w2(const float* __restrict__ in_w, const float* __restrict__ in_b,
                       const float* __restrict__ out_w) {
    int h2 = threadIdx.x;
    int f = blockIdx.x;
    if (f < FIN) {
        float s = 0.f;
        for (int h1 = 0; h1 < HH; h1++) s += in_w[f * HH + h1] * out_w[h1 * HH + h2];
        g_W2[f * HH + h2] = s;
    } else {
        float s = 0.f;
        for (int h1 = 0; h1 < HH; h1++) s += in_b[h1] * out_w[h1 * HH + h2];
        g_b2[h2] = s;
    }
}

// ---------------------------------------------------------------------------
// K4: dual output from x:
//   g_h [b,t,n,h]  = x@in_w + in_b          (residual, exact fp32)
//   g_hw[b,t,n,h2] = tf32(x@W2 + b2)        (k5 B operand)
// grid 2048 = (b, t, nblk of 64), 256 threads (thread = output column)
// ---------------------------------------------------------------------------
__global__ void __launch_bounds__(256) k4_h(const float* __restrict__ x,
                                            const float* __restrict__ in_w,
                                            const float* __restrict__ in_b) {
    int bid = blockIdx.x;
    int nblk = bid & 3;
    int t = (bid >> 2) & 127;
    int b = bid >> 9;
    int tid = threadIdx.x;
    __shared__ float xs[64 * 68];
    for (int idx = tid; idx < 64 * 64; idx += 256) {
        int n = idx >> 6, f = idx & 63;
        xs[n * 68 + f] = x[(((size_t)b * NN + nblk * 64 + n) * TT + t) * FIN + f];
    }
    __syncthreads();

    size_t rowbase = ((size_t)(b * TT + t) * NN + nblk * 64) * HH;
    // pass 1: h (exact fp32 residual)
    {
        float w[FIN];
#pragma unroll
        for (int f = 0; f < FIN; f++) w[f] = in_w[f * HH + tid];
        float bias = in_b[tid];
        float* orow = g_h + rowbase;
        for (int n = 0; n < 64; n++) {
            float acc = bias;
            const float4* xr = (const float4*)&xs[n * 68];
#pragma unroll
            for (int f4 = 0; f4 < 16; f4++) {
                float4 xv = xr[f4];
                acc += xv.x * w[f4 * 4 + 0];
                acc += xv.y * w[f4 * 4 + 1];
                acc += xv.z * w[f4 * 4 + 2];
                acc += xv.w * w[f4 * 4 + 3];
            }
            orow[(size_t)n * HH + tid] = acc;
        }
    }
    // pass 2: hw = x@(in_w@out_w) + in_b@out_w (tf32-rounded; k5 B operand)
    {
        float w[FIN];
#pragma unroll
        for (int f = 0; f < FIN; f++) w[f] = g_W2[f * HH + tid];
        float bias = g_b2[tid];
        float* orow = g_hw + rowbase;
        for (int n = 0; n < 64; n++) {
            float acc = bias;
            const float4* xr = (const float4*)&xs[n * 68];
#pragma unroll
            for (int f4 = 0; f4 < 16; f4++) {
                float4 xv = xr[f4];
                acc += xv.x * w[f4 * 4 + 0];
                acc += xv.y * w[f4 * 4 + 1];
                acc += xv.z * w[f4 * 4 + 2];
                acc += xv.w * w[f4 * 4 + 3];
            }
            orow[(size_t)n * HH + tid] = to_tf32(acc);
        }
    }
}

// ---------------------------------------------------------------------------
// K5: mma.sync tf32 GEMM  Z[i,h2] = sum_j As[b,k][i0+i, j] * hw[b,t-k][j, h2]
//     + out_b + residual + LayerNorm + GELU, transposed store.
// grid = B*T*2 (iblk of 128 rows), 512 threads = 16 warps (4 M x 4 N),
// warp tile 32x64, mma m16n8k8.
// ---------------------------------------------------------------------------
#define A_LD 36
#define B_LD 260
#define STAGE_A_BYTES (128 * A_LD * 4)              // 18432
#define STAGE_BYTES (STAGE_A_BYTES + 32 * B_LD * 4) // 18432 + 33280 = 51712
#define PART_OFF (2 * STAGE_BYTES)                  // 103424
#define SMEM5_BYTES (PART_OFF + 128 * 4 * 8)        // + 4096 = 107520

__device__ __forceinline__ void k5_load_chunk(uint32_t sb, int s, int c,
                                              int b, int t, int i0) {
    int tid = threadIdx.x;
    int k = c >> 3, jt = c & 7;
    const float* Ag = g_As + (((size_t)b * KK + k) * NN + i0) * NN + jt * 32;
    const float* Bg = g_hw + ((size_t)(b * TT + (t - k)) * NN + jt * 32) * HH;
    uint32_t abase = sb + s * STAGE_BYTES;
    uint32_t bbase = abase + STAGE_A_BYTES;
#pragma unroll
    for (int p = 0; p < 2; p++) {
        int idx = tid + p * 512;
        int row = idx >> 3, seg = idx & 7;
        cp16(abase + (row * A_LD + seg * 4) * 4, Ag + (size_t)row * NN + seg * 4);
    }
#pragma unroll
    for (int p = 0; p < 4; p++) {
        int idx = tid + p * 512;
        int jr = idx >> 6, seg = idx & 63;
        cp16(bbase + (jr * B_LD + seg * 4) * 4, Bg + (size_t)jr * HH + seg * 4);
    }
}

__global__ void __launch_bounds__(512) k5_main(const float* __restrict__ out_b,
                                               const float* __restrict__ ln_g,
                                               const float* __restrict__ ln_b,
                                               float* __restrict__ out) {
    extern __shared__ char smem[];
    uint32_t sb = smem_u32(smem);
    int tid = threadIdx.x;
    int wid = tid >> 5, lane = tid & 31;
    int gr = lane >> 2, tg = lane & 3;
    int wr = wid & 3, wc = wid >> 2;  // 4 M-warps x 4 N-warps
    int bid = blockIdx.x;
    int iblk = bid & 1;
    int t = (bid >> 1) & 127;
    int b = bid >> 8;
    int i0 = iblk * 128;
    int nk = min(KK, t + 1);
    int C1 = nk * 8;

    float acc[2][8][4];
#pragma unroll
    for (int mt = 0; mt < 2; mt++)
#pragma unroll
        for (int nt = 0; nt < 8; nt++)
#pragma unroll
            for (int q = 0; q < 4; q++) acc[mt][nt][q] = 0.f;

    k5_load_chunk(sb, 0, 0, b, t, i0);
    CP_COMMIT();

    for (int c = 0; c < C1; c++) {
        int s = c & 1;
        if (c + 1 < C1) {
            k5_load_chunk(sb, s ^ 1, c + 1, b, t, i0);
            CP_COMMIT();
            CP_WAIT1();
        } else {
            CP_WAIT0();
        }
        __syncthreads();
        const uint32_t* As_u = (const uint32_t*)(smem + s * STAGE_BYTES);
        const uint32_t* Bs_u = (const uint32_t*)(smem + s * STAGE_BYTES + STAGE_A_BYTES);
#pragma unroll
        for (int k0 = 0; k0 < 32; k0 += 8) {
            uint32_t af[2][4];
#pragma unroll
            for (int mt = 0; mt < 2; mt++) {
                int rb = wr * 32 + mt * 16;
                const uint32_t* pa = &As_u[(rb + gr) * A_LD + k0 + tg];
                af[mt][0] = pa[0];
                af[mt][1] = pa[8 * A_LD];
                af[mt][2] = pa[4];
                af[mt][3] = pa[8 * A_LD + 4];
            }
            uint32_t bf[8][2];
#pragma unroll
            for (int nt = 0; nt < 8; nt++) {
                int cb = wc * 64 + nt * 8;
                const uint32_t* pb = &Bs_u[(k0 + tg) * B_LD + cb + gr];
                bf[nt][0] = pb[0];
                bf[nt][1] = pb[4 * B_LD];
            }
#pragma unroll
            for (int mt = 0; mt < 2; mt++)
#pragma unroll
                for (int nt = 0; nt < 8; nt++)
                    MMA_TF32(acc[mt][nt], af[mt], bf[nt]);
        }
        __syncthreads();
    }

    // ---------------- epilogue: +out_b +res, LN over H, GELU, store ----------------
    float2* part = (float2*)(smem + PART_OFF);  // [128 rows][4 warp-cols]
    const float2* ob2 = (const float2*)out_b;
    const float2* lg2 = (const float2*)ln_g;
    const float2* lb2 = (const float2*)ln_b;

#pragma unroll
    for (int mt = 0; mt < 2; mt++) {
#pragma unroll
        for (int rr = 0; rr < 2; rr++) {
            int i = wr * 32 + mt * 16 + rr * 8 + gr;
            int ig = i0 + i;
            const float2* res2 =
                (const float2*)(g_h + ((size_t)(b * TT + t) * NN + ig) * HH);
            float s1 = 0.f, s2 = 0.f;
#pragma unroll
            for (int nt = 0; nt < 8; nt++) {
                int h2i = (wc * 64 + nt * 8) / 2 + tg;  // float2 index, h2 = 2*h2i
                float2 rv = res2[h2i];
                float2 bv = ob2[h2i];
                float v0 = acc[mt][nt][rr * 2 + 0] + bv.x + rv.x;
                float v1 = acc[mt][nt][rr * 2 + 1] + bv.y + rv.y;
                acc[mt][nt][rr * 2 + 0] = v0;
                acc[mt][nt][rr * 2 + 1] = v1;
                s1 += v0 + v1;
                s2 += v0 * v0 + v1 * v1;
            }
            s1 += __shfl_xor_sync(0xffffffffu, s1, 1);
            s2 += __shfl_xor_sync(0xffffffffu, s2, 1);
            s1 += __shfl_xor_sync(0xffffffffu, s1, 2);
            s2 += __shfl_xor_sync(0xffffffffu, s2, 2);
            if (tg == 0) part[i * 4 + wc] = make_float2(s1, s2);
        }
    }
    __syncthreads();
#pragma unroll
    for (int mt = 0; mt < 2; mt++) {
#pragma unroll
        for (int rr = 0; rr < 2; rr++) {
            int i = wr * 32 + mt * 16 + rr * 8 + gr;
            int ig = i0 + i;
            float2 p0 = part[i * 4 + 0], p1 = part[i * 4 + 1];
            float2 p2 = part[i * 4 + 2], p3 = part[i * 4 + 3];
            float s1 = p0.x + p1.x + p2.x + p3.x;
            float s2 = p0.y + p1.y + p2.y + p3.y;
            float mu = s1 * (1.0f / HH);
            float var = s2 * (1.0f / HH) - mu * mu;
            float rstd = rsqrtf(var + 1e-5f);
            float* op = out + (((size_t)b * NN + ig) * TT + t) * HH;
#pragma unroll
            for (int nt = 0; nt < 8; nt++) {
                int h2i = (wc * 64 + nt * 8) / 2 + tg;
                float2 gv = lg2[h2i];
                float2 bv = lb2[h2i];
                float y0 = (acc[mt][nt][rr * 2 + 0] - mu) * rstd * gv.x + bv.x;
                float y1 = (acc[mt][nt][rr * 2 + 1] - mu) * rstd * gv.y + bv.y;
                ((float2*)op)[h2i] = make_float2(gelu_exact(y0), gelu_exact(y1));
            }
        }
    }
}

// ---------------------------------------------------------------------------
extern "C" void kernel_launch(void* const* d_in, const int* in_sizes, int n_in,
                              void* d_out, int out_size) {
    const float* x = (const float*)d_in[0];
    const float* A_list = (const float*)d_in[1];
    const float* in_w = (const float*)d_in[2];
    const float* in_b = (const float*)d_in[3];
    const float* out_w = (const float*)d_in[4];
    const float* out_b = (const float*)d_in[5];
    const float* lag_embed = (const float*)d_in[6];
    const float* ctx_w1 = (const float*)d_in[7];
    const float* ctx_b1 = (const float*)d_in[8];
    const float* ctx_w2 = (const float*)d_in[9];
    const float* ctx_b2 = (const float*)d_in[10];
    const float* gate_w1 = (const float*)d_in[11];
    const float* gate_b1 = (const float*)d_in[12];
    const float* gate_w2 = (const float*)d_in[13];
    const float* gate_b2 = (const float*)d_in[14];
    const float* ln_g = (const float*)d_in[15];
    const float* ln_b = (const float*)d_in[16];
    float* out = (float*)d_out;

    cudaFuncSetAttribute(k5_main, cudaFuncAttributeMaxDynamicSharedMemorySize, SMEM5_BYTES);

    k1_ctx<<<64, 256>>>(x);
    k2_gate<<<1, 32>>>(lag_embed, ctx_w1, ctx_b1, ctx_w2, ctx_b2,
                       gate_w1, gate_b1, gate_w2, gate_b2);
    k3_scaleA<<<2048, 256>>>(A_list);
    k3c_w2<<<FIN + 1, 256>>>(in_w, in_b, out_w);
    k4_h<<<2048, 256>>>(x, in_w, in_b);
    k5_main<<<BB * TT * 2, 512, SMEM5_BYTES>>>(out_b, ln_g, ln_b, out);
}

// round 7
// speedup vs baseline: 4.1620x; 1.5911x over previous
#include <cuda_runtime.h>
#include <cuda_bf16.h>
#include <math.h>
#include <stdint.h>

#define BB 4
#define NN 256
#define TT 128
#define FIN 64
#define KK 8
#define HH 256
#define EE 8

// ---------------- scratch (static device globals; no allocation) ----------------
__device__ float g_h[(size_t)BB * TT * NN * HH];            // 128 MB residual (exact fp32)
__device__ __nv_bfloat16 g_hwT[(size_t)BB * TT * HH * NN];  // 64 MB: (b,t,h2,n) n contig
__device__ __nv_bfloat16 g_As[(size_t)BB * KK * NN * NN];   // 4 MB: alpha*A_norm
__device__ float g_W2[FIN * HH];                            // in_w @ out_w
__device__ float g_b2[HH];                                  // in_b @ out_w
__device__ float g_ctx_part[BB * 16 * FIN];
__device__ float g_alpha[BB * KK];

__device__ __forceinline__ float gelu_exact(float v) {
    return 0.5f * v * (1.0f + erff(v * 0.70710678118654752440f));
}
__device__ __forceinline__ uint32_t smem_u32(const void* p) {
    uint32_t a;
    asm("{ .reg .u64 t; cvta.to.shared.u64 t, %1; cvt.u32.u64 %0, t; }" : "=r"(a) : "l"(p));
    return a;
}
__device__ __forceinline__ void cp16(uint32_t dst, const void* src) {
    asm volatile("cp.async.cg.shared.global [%0], [%1], 16;" :: "r"(dst), "l"(src));
}
#define CP_COMMIT() asm volatile("cp.async.commit_group;" ::: "memory")
#define CP_WAIT0() asm volatile("cp.async.wait_group 0;" ::: "memory")
#define CP_WAIT1() asm volatile("cp.async.wait_group 1;" ::: "memory")

#define MMA_BF16(d, a, b) \
    asm volatile("mma.sync.aligned.m16n8k16.row.col.f32.bf16.bf16.f32 " \
        "{%0,%1,%2,%3}, {%4,%5,%6,%7}, {%8,%9}, {%0,%1,%2,%3};" \
        : "+f"((d)[0]), "+f"((d)[1]), "+f"((d)[2]), "+f"((d)[3]) \
        : "r"((a)[0]), "r"((a)[1]), "r"((a)[2]), "r"((a)[3]), "r"((b)[0]), "r"((b)[1]))

// ---------------------------------------------------------------------------
// K1: partial sums for ctx = x.mean(axis=(1,2))
// ---------------------------------------------------------------------------
__global__ void k1_ctx(const float* __restrict__ x) {
    int b = blockIdx.x >> 4;
    int ch = blockIdx.x & 15;
    int f = threadIdx.x & 63;
    int part = threadIdx.x >> 6;
    const float* xb = x + (size_t)b * NN * TT * FIN;
    float s = 0.f;
    int nt0 = ch * 2048;
    for (int nt = nt0 + part; nt < nt0 + 2048; nt += 4)
        s += xb[(size_t)nt * FIN + f];
    __shared__ float sred[256];
    sred[threadIdx.x] = s;
    __syncthreads();
    if (part == 0) {
        float tot = sred[f] + sred[64 + f] + sred[128 + f] + sred[192 + f];
        g_ctx_part[(b * 16 + ch) * FIN + f] = tot;
    }
}

// ---------------------------------------------------------------------------
// K2: ctx MLP + gate MLP -> alpha[b,k]
// ---------------------------------------------------------------------------
__global__ void k2_gate(const float* __restrict__ lag_embed,
                        const float* __restrict__ ctx_w1, const float* __restrict__ ctx_b1,
                        const float* __restrict__ ctx_w2, const float* __restrict__ ctx_b2,
                        const float* __restrict__ gate_w1, const float* __restrict__ gate_b1,
                        const float* __restrict__ gate_w2, const float* __restrict__ gate_b2) {
    int tid = threadIdx.x;
    if (tid >= BB * KK) return;
    int b = tid >> 3, k = tid & 7;
    float ctx[FIN];
    for (int f = 0; f < FIN; f++) {
        float s = 0.f;
        for (int ch = 0; ch < 16; ch++) s += g_ctx_part[(b * 16 + ch) * FIN + f];
        ctx[f] = s * (1.0f / (NN * TT));
    }
    float t1[EE];
    for (int e = 0; e < EE; e++) {
        float s = ctx_b1[e];
        for (int f = 0; f < FIN; f++) s += ctx[f] * ctx_w1[f * EE + e];
        t1[e] = gelu_exact(s);
    }
    float cf[EE];
    for (int e2 = 0; e2 < EE; e2++) {
        float s = ctx_b2[e2];
        for (int e = 0; e < EE; e++) s += t1[e] * ctx_w2[e * EE + e2];
        cf[e2] = s;
    }
    float gi[2 * EE];
    for (int e = 0; e < EE; e++) { gi[e] = lag_embed[k * EE + e]; gi[EE + e] = cf[e]; }
    float hid[EE];
    for (int e = 0; e < EE; e++) {
        float s = gate_b1[e];
        for (int j = 0; j < 2 * EE; j++) s += gi[j] * gate_w1[j * EE + e];
        hid[e] = gelu_exact(s);
    }
    float val = gate_b2[0];
    for (int e = 0; e < EE; e++) val += hid[e] * gate_w2[e];
    g_alpha[tid] = 1.0f / (1.0f + expf(-val));
}

// ---------------------------------------------------------------------------
// K3: g_As[b,k,i,j] = bf16( alpha[b,k] * A[k,i,j] / max(rowsum, 1e-8) )
// ---------------------------------------------------------------------------
__global__ void k3_scaleA(const float* __restrict__ A_list) {
    int k = blockIdx.x >> 8;
    int i = blockIdx.x & 255;
    int tid = threadIdx.x;
    float a = A_list[((size_t)k * NN + i) * NN + tid];
    __shared__ float sred[256];
    sred[tid] = a;
    __syncthreads();
    for (int s = 128; s > 0; s >>= 1) {
        if (tid < s) sred[tid] += sred[tid + s];
        __syncthreads();
    }
    float inv = 1.0f / fmaxf(sred[0], 1e-8f);
    float an = a * inv;
#pragma unroll
    for (int b = 0; b < BB; b++)
        g_As[(((size_t)b * KK + k) * NN + i) * NN + tid] =
            __float2bfloat16(g_alpha[b * KK + k] * an);
}

// ---------------------------------------------------------------------------
// K3c: g_W2 = in_w @ out_w  (f,h2), g_b2 = in_b @ out_w. grid 65 x 256
// ---------------------------------------------------------------------------
__global__ void k3c_w2(const float* __restrict__ in_w, const float* __restrict__ in_b,
                       const float* __restrict__ out_w) {
    int h2 = threadIdx.x;
    int f = blockIdx.x;
    if (f < FIN) {
        float s = 0.f;
        for (int h1 = 0; h1 < HH; h1++) s += in_w[f * HH + h1] * out_w[h1 * HH + h2];
        g_W2[f * HH + h2] = s;
    } else {
        float s = 0.f;
        for (int h1 = 0; h1 < HH; h1++) s += in_b[h1] * out_w[h1 * HH + h2];
        g_b2[h2] = s;
    }
}

// ---------------------------------------------------------------------------
// K4: dual output from x:
//   g_h  [b,t,n,h]  = x@in_w + in_b          (residual, exact fp32)
//   g_hwT[b,t,h2,n] = bf16(x@W2 + b2)        (k5 B operand, transposed)
// grid 2048 = (b, t, nblk of 64), 256 threads (thread = output column)
// ---------------------------------------------------------------------------
#define SH2_LD 36

__global__ void __launch_bounds__(256) k4_h(const float* __restrict__ x,
                                            const float* __restrict__ in_w,
                                            const float* __restrict__ in_b) {
    int bid = blockIdx.x;
    int nblk = bid & 3;
    int t = (bid >> 2) & 127;
    int b = bid >> 9;
    int tid = threadIdx.x;
    __shared__ float xs[64 * 68];
    __shared__ __nv_bfloat16 sh2[256 * SH2_LD];
    for (int idx = tid; idx < 64 * 64; idx += 256) {
        int n = idx >> 6, f = idx & 63;
        xs[n * 68 + f] = x[(((size_t)b * NN + nblk * 64 + n) * TT + t) * FIN + f];
    }
    __syncthreads();

    // pass 1: h (exact fp32 residual)
    {
        float w[FIN];
#pragma unroll
        for (int f = 0; f < FIN; f++) w[f] = in_w[f * HH + tid];
        float bias = in_b[tid];
        float* orow = g_h + ((size_t)(b * TT + t) * NN + nblk * 64) * HH;
        for (int n = 0; n < 64; n++) {
            float acc = bias;
            const float4* xr = (const float4*)&xs[n * 68];
#pragma unroll
            for (int f4 = 0; f4 < 16; f4++) {
                float4 xv = xr[f4];
                acc += xv.x * w[f4 * 4 + 0];
                acc += xv.y * w[f4 * 4 + 1];
                acc += xv.z * w[f4 * 4 + 2];
                acc += xv.w * w[f4 * 4 + 3];
            }
            orow[(size_t)n * HH + tid] = acc;
        }
    }
    // pass 2: hw = x@W2 + b2, bf16, store TRANSPOSED (h2 rows, n contig)
    {
        float w[FIN];
#pragma unroll
        for (int f = 0; f < FIN; f++) w[f] = g_W2[f * HH + tid];
        float bias = g_b2[tid];
        uint32_t* dstbase = (uint32_t*)g_hwT +
            ((size_t)(b * TT + t) * HH) * (NN / 2) + (nblk * 64) / 2;
        for (int half = 0; half < 2; half++) {
            for (int n0 = 0; n0 < 32; n0++) {
                int n = half * 32 + n0;
                float acc = bias;
                const float4* xr = (const float4*)&xs[n * 68];
#pragma unroll
                for (int f4 = 0; f4 < 16; f4++) {
                    float4 xv = xr[f4];
                    acc += xv.x * w[f4 * 4 + 0];
                    acc += xv.y * w[f4 * 4 + 1];
                    acc += xv.z * w[f4 * 4 + 2];
                    acc += xv.w * w[f4 * 4 + 3];
                }
                sh2[tid * SH2_LD + n0] = __float2bfloat16(acc);
            }
            __syncthreads();
            // flush 256 x 32 bf16 tile, coalesced
#pragma unroll
            for (int j = 0; j < 16; j++) {
                int idx = tid + j * 256;
                int h2 = idx >> 4, w16 = idx & 15;
                uint32_t v = *(const uint32_t*)&sh2[h2 * SH2_LD + w16 * 2];
                dstbase[(size_t)h2 * (NN / 2) + half * 16 + w16] = v;
            }
            __syncthreads();
        }
    }
}

// ---------------------------------------------------------------------------
// K5: bf16 mma GEMM  Z[i,h2] = sum_j As[b,k][i0+i, j] * hw[b,t-k][j, h2]
//     + out_b + residual + LayerNorm + GELU, transposed store.
// grid = B*T*2 (iblk of 128 rows), 512 threads = 16 warps (4 M x 4 N),
// warp tile 32x64, mma m16n8k16, K-chunk = 64.
// A smem: [i][k] 128x64 bf16 (LD 72). B smem: [h2][k] 256x64 bf16 (LD 72).
// ---------------------------------------------------------------------------
#define A_LD 72
#define B_LD 72
#define STAGE_A_BYTES (128 * A_LD * 2)               // 18432
#define STAGE_BYTES (STAGE_A_BYTES + 256 * B_LD * 2) // 18432 + 36864 = 55296
#define PART_OFF (2 * STAGE_BYTES)                   // 110592
#define SMEM5_BYTES (PART_OFF + 128 * 4 * 8)         // + 4096 = 114688

__device__ __forceinline__ void k5_load_chunk(uint32_t sb, int s, int c,
                                              int b, int t, int i0) {
    int tid = threadIdx.x;
    int k = c >> 2, jt = c & 3;  // jt selects 64-wide j slice
    const __nv_bfloat16* Ag = g_As + (((size_t)b * KK + k) * NN + i0) * NN + jt * 64;
    const __nv_bfloat16* Bg = g_hwT + ((size_t)(b * TT + (t - k)) * HH) * NN + jt * 64;
    uint32_t abase = sb + s * STAGE_BYTES;
    uint32_t bbase = abase + STAGE_A_BYTES;
#pragma unroll
    for (int p = 0; p < 2; p++) {
        int idx = tid + p * 512;
        int row = idx >> 3, seg = idx & 7;  // 128 rows x 8 segs of 16B
        cp16(abase + (row * A_LD + seg * 8) * 2, Ag + (size_t)row * NN + seg * 8);
    }
#pragma unroll
    for (int p = 0; p < 4; p++) {
        int idx = tid + p * 512;
        int row = idx >> 3, seg = idx & 7;  // 256 rows x 8 segs
        cp16(bbase + (row * B_LD + seg * 8) * 2, Bg + (size_t)row * NN + seg * 8);
    }
}

__global__ void __launch_bounds__(512) k5_main(const float* __restrict__ out_b,
                                               const float* __restrict__ ln_g,
                                               const float* __restrict__ ln_b,
                                               float* __restrict__ out) {
    extern __shared__ char smem[];
    uint32_t sb = smem_u32(smem);
    int tid = threadIdx.x;
    int wid = tid >> 5, lane = tid & 31;
    int gr = lane >> 2, tg = lane & 3;
    int wr = wid & 3, wc = wid >> 2;  // 4 M-warps x 4 N-warps
    int bid = blockIdx.x;
    int iblk = bid & 1;
    int t = (bid >> 1) & 127;
    int b = bid >> 8;
    int i0 = iblk * 128;
    int nk = min(KK, t + 1);
    int C1 = nk * 4;

    float acc[2][8][4];
#pragma unroll
    for (int mt = 0; mt < 2; mt++)
#pragma unroll
        for (int nt = 0; nt < 8; nt++)
#pragma unroll
            for (int q = 0; q < 4; q++) acc[mt][nt][q] = 0.f;

    k5_load_chunk(sb, 0, 0, b, t, i0);
    CP_COMMIT();

    for (int c = 0; c < C1; c++) {
        int s = c & 1;
        if (c + 1 < C1) {
            k5_load_chunk(sb, s ^ 1, c + 1, b, t, i0);
            CP_COMMIT();
            CP_WAIT1();
        } else {
            CP_WAIT0();
        }
        __syncthreads();
        const __nv_bfloat16* As_s = (const __nv_bfloat16*)(smem + s * STAGE_BYTES);
        const __nv_bfloat16* Bs_s = (const __nv_bfloat16*)(smem + s * STAGE_BYTES + STAGE_A_BYTES);
#pragma unroll
        for (int ks = 0; ks < 4; ks++) {
            int kb = ks * 16;
            uint32_t af[2][4];
#pragma unroll
            for (int mt = 0; mt < 2; mt++) {
                int rb = wr * 32 + mt * 16;
                const __nv_bfloat16* pa = As_s + (rb + gr) * A_LD + kb + 2 * tg;
                af[mt][0] = *(const uint32_t*)(pa);
                af[mt][1] = *(const uint32_t*)(pa + 8 * A_LD);
                af[mt][2] = *(const uint32_t*)(pa + 8);
                af[mt][3] = *(const uint32_t*)(pa + 8 * A_LD + 8);
            }
            uint32_t bf[8][2];
#pragma unroll
            for (int nt = 0; nt < 8; nt++) {
                int n = wc * 64 + nt * 8 + gr;
                const __nv_bfloat16* pb = Bs_s + n * B_LD + kb + 2 * tg;
                bf[nt][0] = *(const uint32_t*)(pb);
                bf[nt][1] = *(const uint32_t*)(pb + 8);
            }
#pragma unroll
            for (int mt = 0; mt < 2; mt++)
#pragma unroll
                for (int nt = 0; nt < 8; nt++)
                    MMA_BF16(acc[mt][nt], af[mt], bf[nt]);
        }
        __syncthreads();
    }

    // ---------------- epilogue: +out_b +res, LN over H, GELU, store ----------------
    float2* part = (float2*)(smem + PART_OFF);  // [128 rows][4 warp-cols]
    const float2* ob2 = (const float2*)out_b;
    const float2* lg2 = (const float2*)ln_g;
    const float2* lb2 = (const float2*)ln_b;

#pragma unroll
    for (int mt = 0; mt < 2; mt++) {
#pragma unroll
        for (int rr = 0; rr < 2; rr++) {
            int i = wr * 32 + mt * 16 + rr * 8 + gr;
            int ig = i0 + i;
            const float2* res2 =
                (const float2*)(g_h + ((size_t)(b * TT + t) * NN + ig) * HH);
            float s1 = 0.f, s2 = 0.f;
#pragma unroll
            for (int nt = 0; nt < 8; nt++) {
                int h2i = (wc * 64 + nt * 8) / 2 + tg;  // float2 index, h2 = 2*h2i
                float2 rv = res2[h2i];
                float2 bv = ob2[h2i];
                float v0 = acc[mt][nt][rr * 2 + 0] + bv.x + rv.x;
                float v1 = acc[mt][nt][rr * 2 + 1] + bv.y + rv.y;
                acc[mt][nt][rr * 2 + 0] = v0;
                acc[mt][nt][rr * 2 + 1] = v1;
                s1 += v0 + v1;
                s2 += v0 * v0 + v1 * v1;
            }
            s1 += __shfl_xor_sync(0xffffffffu, s1, 1);
            s2 += __shfl_xor_sync(0xffffffffu, s2, 1);
            s1 += __shfl_xor_sync(0xffffffffu, s1, 2);
            s2 += __shfl_xor_sync(0xffffffffu, s2, 2);
            if (tg == 0) part[i * 4 + wc] = make_float2(s1, s2);
        }
    }
    __syncthreads();
#pragma unroll
    for (int mt = 0; mt < 2; mt++) {
#pragma unroll
        for (int rr = 0; rr < 2; rr++) {
            int i = wr * 32 + mt * 16 + rr * 8 + gr;
            int ig = i0 + i;
            float2 p0 = part[i * 4 + 0], p1 = part[i * 4 + 1];
            float2 p2 = part[i * 4 + 2], p3 = part[i * 4 + 3];
            float s1 = p0.x + p1.x + p2.x + p3.x;
            float s2 = p0.y + p1.y + p2.y + p3.y;
            float mu = s1 * (1.0f / HH);
            float var = s2 * (1.0f / HH) - mu * mu;
            float rstd = rsqrtf(var + 1e-5f);
            float* op = out + (((size_t)b * NN + ig) * TT + t) * HH;
#pragma unroll
            for (int nt = 0; nt < 8; nt++) {
                int h2i = (wc * 64 + nt * 8) / 2 + tg;
                float2 gv = lg2[h2i];
                float2 bv = lb2[h2i];
                float y0 = (acc[mt][nt][rr * 2 + 0] - mu) * rstd * gv.x + bv.x;
                float y1 = (acc[mt][nt][rr * 2 + 1] - mu) * rstd * gv.y + bv.y;
                ((float2*)op)[h2i] = make_float2(gelu_exact(y0), gelu_exact(y1));
            }
        }
    }
}

// ---------------------------------------------------------------------------
extern "C" void kernel_launch(void* const* d_in, const int* in_sizes, int n_in,
                              void* d_out, int out_size) {
    const float* x = (const float*)d_in[0];
    const float* A_list = (const float*)d_in[1];
    const float* in_w = (const float*)d_in[2];
    const float* in_b = (const float*)d_in[3];
    const float* out_w = (const float*)d_in[4];
    const float* out_b = (const float*)d_in[5];
    const float* lag_embed = (const float*)d_in[6];
    const float* ctx_w1 = (const float*)d_in[7];
    const float* ctx_b1 = (const float*)d_in[8];
    const float* ctx_w2 = (const float*)d_in[9];
    const float* ctx_b2 = (const float*)d_in[10];
    const float* gate_w1 = (const float*)d_in[11];
    const float* gate_b1 = (const float*)d_in[12];
    const float* gate_w2 = (const float*)d_in[13];
    const float* gate_b2 = (const float*)d_in[14];
    const float* ln_g = (const float*)d_in[15];
    const float* ln_b = (const float*)d_in[16];
    float* out = (float*)d_out;

    cudaFuncSetAttribute(k5_main, cudaFuncAttributeMaxDynamicSharedMemorySize, SMEM5_BYTES);

    k1_ctx<<<64, 256>>>(x);
    k2_gate<<<1, 32>>>(lag_embed, ctx_w1, ctx_b1, ctx_w2, ctx_b2,
                       gate_w1, gate_b1, gate_w2, gate_b2);
    k3_scaleA<<<2048, 256>>>(A_list);
    k3c_w2<<<FIN + 1, 256>>>(in_w, in_b, out_w);
    k4_h<<<2048, 256>>>(x, in_w, in_b);
    k5_main<<<BB * TT * 2, 512, SMEM5_BYTES>>>(out_b, ln_g, ln_b, out);
}